// round 1
// baseline (speedup 1.0000x reference)
#include <cuda_runtime.h>
#include <cstdint>

// ---------------------------------------------------------------------------
// Problem constants: B=4, S=2048, D=1024, H=16, dk=64
//   M = B*S = 8192 rows, N = K = 1024 for all dense GEMMs.
// Reshape trick: (X@W) [B,2048,1024] viewed row-major as [B*32768, 64]
//   puts head h at contiguous rows [bh*2048, bh*2048+2048), bh = b*16+h.
// ---------------------------------------------------------------------------
#define MROWS 8192
#define NCOLS 1024
#define KDIM  1024
#define SEQ   2048
#define NHEAD 16
#define DK    64
#define NBATCH 4

// Scratch (device globals: allocation at module load, allowed by harness rules)
__device__ float g_xq[NBATCH * SEQ * NCOLS];
__device__ float g_xk[NBATCH * SEQ * NCOLS];
__device__ float g_xv[NBATCH * SEQ * NCOLS];
__device__ float g_ctx[NBATCH * SEQ * NCOLS];

// ---------------------------------------------------------------------------
// SGEMM body: C[8192,1024] = A[8192,1024] @ B[1024,1024]
// 128x128 tile, BK=16, 256 threads, 8x8 per-thread register tile.
// ---------------------------------------------------------------------------
__device__ __forceinline__ void gemm_body(const float* __restrict__ A,
                                          const float* __restrict__ B,
                                          float* __restrict__ C) {
    __shared__ float As[16][128];
    __shared__ float Bs[16][128];

    const int tid  = threadIdx.x;
    const int row0 = blockIdx.y * 128;
    const int col0 = blockIdx.x * 128;
    const int ty = tid >> 4;   // 0..15
    const int tx = tid & 15;   // 0..15

    // A-tile load mapping: 512 float4 total (128 rows x 4), 2 per thread, same row.
    const int l    = tid * 2;
    const int arow = l >> 2;         // 0..127
    const int ac   = (l & 3) * 4;    // 0 or 8
    // B-tile load mapping: 512 float4 (16 rows x 32), 2 per thread, same row.
    const int brow = l >> 5;         // 0..15
    const int bc   = (l & 31) * 4;   // 0..124 step 8

    const float* Aptr = A + (size_t)(row0 + arow) * KDIM;

    float acc[8][8];
#pragma unroll
    for (int i = 0; i < 8; i++)
#pragma unroll
        for (int j = 0; j < 8; j++) acc[i][j] = 0.f;

    for (int kk = 0; kk < KDIM; kk += 16) {
        float4 a0 = *(const float4*)(Aptr + kk + ac);
        float4 a1 = *(const float4*)(Aptr + kk + ac + 4);
        As[ac + 0][arow] = a0.x; As[ac + 1][arow] = a0.y;
        As[ac + 2][arow] = a0.z; As[ac + 3][arow] = a0.w;
        As[ac + 4][arow] = a1.x; As[ac + 5][arow] = a1.y;
        As[ac + 6][arow] = a1.z; As[ac + 7][arow] = a1.w;

        const float* Brow = B + (size_t)(kk + brow) * NCOLS + col0 + bc;
        float4 b0 = *(const float4*)(Brow);
        float4 b1 = *(const float4*)(Brow + 4);
        *(float4*)&Bs[brow][bc]     = b0;
        *(float4*)&Bs[brow][bc + 4] = b1;

        __syncthreads();

#pragma unroll
        for (int k = 0; k < 16; k++) {
            float ar[8], br[8];
            *(float4*)(ar)     = *(const float4*)&As[k][ty * 8];
            *(float4*)(ar + 4) = *(const float4*)&As[k][ty * 8 + 4];
            *(float4*)(br)     = *(const float4*)&Bs[k][tx * 8];
            *(float4*)(br + 4) = *(const float4*)&Bs[k][tx * 8 + 4];
#pragma unroll
            for (int i = 0; i < 8; i++)
#pragma unroll
                for (int j = 0; j < 8; j++)
                    acc[i][j] += ar[i] * br[j];
        }
        __syncthreads();
    }

#pragma unroll
    for (int i = 0; i < 8; i++) {
        float* Crow = C + (size_t)(row0 + ty * 8 + i) * NCOLS + col0 + tx * 8;
        *(float4*)(Crow)     = make_float4(acc[i][0], acc[i][1], acc[i][2], acc[i][3]);
        *(float4*)(Crow + 4) = make_float4(acc[i][4], acc[i][5], acc[i][6], acc[i][7]);
    }
}

// Fused Q/K/V projections: grid.z selects which projection.
__global__ void __launch_bounds__(256, 1)
proj3_kernel(const float* __restrict__ Q, const float* __restrict__ K,
             const float* __restrict__ V, const float* __restrict__ WQ,
             const float* __restrict__ WK, const float* __restrict__ WV) {
    const float* A; const float* W; float* C;
    if (blockIdx.z == 0)      { A = Q; W = WQ; C = g_xq; }
    else if (blockIdx.z == 1) { A = K; W = WK; C = g_xk; }
    else                      { A = V; W = WV; C = g_xv; }
    gemm_body(A, W, C);
}

// Output projection: out = g_ctx @ Wfc
__global__ void __launch_bounds__(256, 1)
projout_kernel(const float* __restrict__ Wfc, float* __restrict__ out) {
    gemm_body(g_ctx, Wfc, out);
}

// ---------------------------------------------------------------------------
// Flash-style attention (fp32, exact softmax over full 2048 keys).
// Grid: (8 q-tiles, 64 bh). 256 threads; thread t owns query row tile*256+t.
// K/V staged in dynamic shared, 128 keys per stage.
// ---------------------------------------------------------------------------
__global__ void __launch_bounds__(256, 1)
attn_kernel() {
    extern __shared__ float sh[];        // Ks[128*64] | Vs[128*64] = 64 KB
    float* Ks = sh;
    float* Vs = sh + 128 * 64;

    const int tid = threadIdx.x;
    const int bh  = blockIdx.y;          // 0..63  (= b*16 + h)
    const int b   = bh >> 4;
    const int h   = bh & 15;
    const size_t headBase = (size_t)bh * SEQ * DK;
    const int s = blockIdx.x * 256 + tid;   // query sequence index

    // Load q row into registers.
    float q[64];
    const float* qp = g_xq + headBase + (size_t)s * DK;
#pragma unroll
    for (int i = 0; i < 16; i++)
        *(float4*)(q + 4 * i) = *(const float4*)(qp + 4 * i);

    float o[64];
#pragma unroll
    for (int d = 0; d < 64; d++) o[d] = 0.f;
    float m = -1e30f, lsum = 0.f;

    for (int kt = 0; kt < 16; kt++) {
        const float4* kp = (const float4*)(g_xk + headBase + (size_t)kt * 128 * DK);
        const float4* vp = (const float4*)(g_xv + headBase + (size_t)kt * 128 * DK);
#pragma unroll
        for (int i = 0; i < 8; i++) {
            ((float4*)Ks)[tid + i * 256] = kp[tid + i * 256];
            ((float4*)Vs)[tid + i * 256] = vp[tid + i * 256];
        }
        __syncthreads();

        for (int jc = 0; jc < 8; jc++) {
            float sc[16];
#pragma unroll
            for (int jj = 0; jj < 16; jj++) {
                const float4* kr = (const float4*)(Ks + (jc * 16 + jj) * 64);
                float a = 0.f;
#pragma unroll
                for (int d = 0; d < 16; d++) {
                    float4 kv = kr[d];
                    a += q[4 * d]     * kv.x;
                    a += q[4 * d + 1] * kv.y;
                    a += q[4 * d + 2] * kv.z;
                    a += q[4 * d + 3] * kv.w;
                }
                sc[jj] = a * 0.125f;   // 1/sqrt(64)
            }
            float cmax = sc[0];
#pragma unroll
            for (int jj = 1; jj < 16; jj++) cmax = fmaxf(cmax, sc[jj]);
            float mn   = fmaxf(m, cmax);
            float corr = __expf(m - mn);
            lsum *= corr;
#pragma unroll
            for (int d = 0; d < 64; d++) o[d] *= corr;
            m = mn;
#pragma unroll
            for (int jj = 0; jj < 16; jj++) {
                float p = __expf(sc[jj] - m);
                lsum += p;
                const float4* vr = (const float4*)(Vs + (jc * 16 + jj) * 64);
#pragma unroll
                for (int d = 0; d < 16; d++) {
                    float4 vv = vr[d];
                    o[4 * d]     += p * vv.x;
                    o[4 * d + 1] += p * vv.y;
                    o[4 * d + 2] += p * vv.z;
                    o[4 * d + 3] += p * vv.w;
                }
            }
        }
        __syncthreads();
    }

    // Write ctx with the transpose(0,2,1,3) layout: ctx[b, s, h*64 + d]
    const float inv = 1.f / lsum;
    float* op = g_ctx + (size_t)b * SEQ * NCOLS + (size_t)s * NCOLS + h * DK;
#pragma unroll
    for (int i = 0; i < 16; i++) {
        float4 v = make_float4(o[4 * i] * inv, o[4 * i + 1] * inv,
                               o[4 * i + 2] * inv, o[4 * i + 3] * inv);
        ((float4*)op)[i] = v;
    }
}

// ---------------------------------------------------------------------------
// kernel_launch — graph-capturable, allocation-free.
// Inputs (metadata order): Q, K, V, WQ, WK, WV, Wfc. Output: [4,2048,1024] f32.
// ---------------------------------------------------------------------------
extern "C" void kernel_launch(void* const* d_in, const int* in_sizes, int n_in,
                              void* d_out, int out_size) {
    const float* Q   = (const float*)d_in[0];
    const float* K   = (const float*)d_in[1];
    const float* V   = (const float*)d_in[2];
    const float* WQ  = (const float*)d_in[3];
    const float* WK  = (const float*)d_in[4];
    const float* WV  = (const float*)d_in[5];
    const float* Wfc = (const float*)d_in[6];
    float* out = (float*)d_out;

    (void)in_sizes; (void)n_in; (void)out_size;

    // 64 KB dynamic smem for the attention kernel (above 48 KB default).
    cudaFuncSetAttribute(attn_kernel,
                         cudaFuncAttributeMaxDynamicSharedMemorySize, 65536);

    // 1) Q/K/V projections (fused launch, grid.z = which projection)
    dim3 gGemm(NCOLS / 128, MROWS / 128, 3);
    proj3_kernel<<<gGemm, 256>>>(Q, K, V, WQ, WK, WV);

    // 2) attention: 8 q-tiles x 64 (b,h)
    dim3 gAttn(SEQ / 256, NBATCH * NHEAD);
    attn_kernel<<<gAttn, 256, 65536>>>();

    // 3) output projection
    dim3 gOut(NCOLS / 128, MROWS / 128, 1);
    projout_kernel<<<gOut, 256>>>(Wfc, out);
}